// round 13
// baseline (speedup 1.0000x reference)
#include <cuda_runtime.h>
#include <cuda_fp16.h>
#include <math.h>
#include <stdint.h>

typedef unsigned long long ull;

// ---------------- device globals (scratch; no allocations allowed) ----------
__device__ __half  g_data[8192 * 512]; // fp16 concatenated [source; target]
__device__ float   g_sq[8192];         // per-row squared L2 norms (fp32)
__device__ float   g_colA[512];        // column sums (atomic accum)
__device__ double  g_sqsum;            // total sq-norm sum (atomic accum)
__device__ int     g_done2;            // gemm completion counter
__device__ int     g_ccflag;           // bandwidth coefficient ready
__device__ double  g_acc[4];           // quadrant sums [XX, XY, YX, YY]
__device__ float   g_cc;               // -log2(e) / (bw * 16)

// ---------------- PTX helpers ----------------------------------------------
__device__ __forceinline__ float ex2f(float x) {
    float y; asm("ex2.approx.ftz.f32 %0, %1;" : "=f"(y) : "f"(x)); return y;
}
__device__ __forceinline__ uint32_t smem_u32(const void* p) {
    uint32_t a;
    asm("{ .reg .u64 t; cvta.to.shared.u64 t, %1; cvt.u32.u64 %0, t; }" : "=r"(a) : "l"(p));
    return a;
}
__device__ __forceinline__ void cp_async16(uint32_t saddr, const void* g) {
    asm volatile("cp.async.cg.shared.global [%0], [%1], 16;" :: "r"(saddr), "l"(g));
}
#define CP_COMMIT()  asm volatile("cp.async.commit_group;" ::: "memory")
#define CP_WAIT1()   asm volatile("cp.async.wait_group 1;" ::: "memory")

__device__ __forceinline__ void ldsm4(uint32_t& r0, uint32_t& r1, uint32_t& r2,
                                      uint32_t& r3, uint32_t addr) {
    asm volatile("ldmatrix.sync.aligned.m8n8.x4.shared.b16 {%0,%1,%2,%3}, [%4];"
                 : "=r"(r0), "=r"(r1), "=r"(r2), "=r"(r3) : "r"(addr));
}
__device__ __forceinline__ void hmma(float* d, const uint32_t* a, uint32_t b0, uint32_t b1) {
    asm volatile(
        "mma.sync.aligned.m16n8k16.row.col.f32.f16.f16.f32 "
        "{%0,%1,%2,%3}, {%4,%5,%6,%7}, {%8,%9}, {%0,%1,%2,%3};"
        : "+f"(d[0]), "+f"(d[1]), "+f"(d[2]), "+f"(d[3])
        : "r"(a[0]), "r"(a[1]), "r"(a[2]), "r"(a[3]), "r"(b0), "r"(b1));
}

// ---------------- kernel 1: prep (pure producer) ----------------------------
__global__ __launch_bounds__(256)
void k_prep(const float* __restrict__ src, const float* __restrict__ tgt) {
    __shared__ float scol[512];
    int tid = threadIdx.x, w = tid >> 5, lane = tid & 31;

    for (int i = tid; i < 512; i += 256) scol[i] = 0.f;

    int row0 = blockIdx.x * 16 + w * 2;
    const float* p0 = (row0 < 4096) ? src + (size_t)row0 * 512
                                    : tgt + (size_t)(row0 - 4096) * 512;
    const float* p1 = p0 + 512;

    float4 v[2][4];
#pragma unroll
    for (int c = 0; c < 4; c++) v[0][c] = *(const float4*)(p0 + lane * 4 + c * 128);
#pragma unroll
    for (int c = 0; c < 4; c++) v[1][c] = *(const float4*)(p1 + lane * 4 + c * 128);

    float colacc[16];
#pragma unroll
    for (int i = 0; i < 16; i++) colacc[i] = 0.f;
    double warp_sq = 0.0;
    __syncthreads();

#pragma unroll
    for (int rr = 0; rr < 2; rr++) {
        int row = row0 + rr;
        float s = 0.f;
#pragma unroll
        for (int c = 0; c < 4; c++) {
            float4 q = v[rr][c];
            uint2 o;
            asm("cvt.rn.f16x2.f32 %0, %1, %2;" : "=r"(o.x) : "f"(q.y), "f"(q.x));
            asm("cvt.rn.f16x2.f32 %0, %1, %2;" : "=r"(o.y) : "f"(q.w), "f"(q.z));
            *(uint2*)(g_data + (size_t)row * 512 + lane * 4 + c * 128) = o;
            s = fmaf(q.x, q.x, s); s = fmaf(q.y, q.y, s);
            s = fmaf(q.z, q.z, s); s = fmaf(q.w, q.w, s);
            colacc[c * 4 + 0] += q.x; colacc[c * 4 + 1] += q.y;
            colacc[c * 4 + 2] += q.z; colacc[c * 4 + 3] += q.w;
        }
#pragma unroll
        for (int o = 16; o; o >>= 1) s += __shfl_xor_sync(0xffffffffu, s, o);
        if (lane == 0) { g_sq[row] = s; warp_sq += (double)s; }
    }

#pragma unroll
    for (int c = 0; c < 4; c++)
#pragma unroll
        for (int j = 0; j < 4; j++)
            atomicAdd(&scol[lane * 4 + c * 128 + j], colacc[c * 4 + j]);
    __syncthreads();

    for (int i = tid; i < 512; i += 256) atomicAdd(&g_colA[i], scol[i]);
    if (lane == 0) atomicAdd(&g_sqsum, warp_sq);
}

// ---------------- kernel 2: mma.sync fp16 GEMM + epilogue + final -----------
// CTA tile 128x128, triangular over 64x64 blocks -> 2080 CTAs.
// 4 warps (2m x 2n), warp tile 64x64, 128 threads, 2 CTAs/SM.
// K=512 in 8 chunks of 64 (4 ks phases), 3-stage cp.async pipeline.
// B frags double-buffered across phases; A frags pipelined per-mt;
// LDGSTS spread as 4 quarters across phases.
static constexpr int KT = 8;
static constexpr int A_BYTES = 16384;       // 128 rows x 128B
static constexpr int STAGE_BYTES = 32768;   // A 16KB + B 16KB
static constexpr int SMEM_TOTAL = 3 * STAGE_BYTES;  // 98304

__global__ __launch_bounds__(128, 2)
void k_mma(float* __restrict__ out) {
    extern __shared__ char sm[];
    uint32_t sbase = smem_u32(sm);

    int tid = threadIdx.x;
    int wid = tid >> 5, lane = tid & 31;

    // CTA 0: compute g_cc (inputs complete at kernel boundary), publish flag.
    if (blockIdx.x == 0) {
        double* sredc = (double*)sm;
        double csq = 0.0;
#pragma unroll
        for (int j = 0; j < 4; j++) {
            double c = (double)g_colA[tid + j * 128];
            csq += c * c;
        }
        sredc[tid] = csq;
        __syncthreads();
        for (int o = 64; o; o >>= 1) { if (tid < o) sredc[tid] += sredc[tid + o]; __syncthreads(); }
        if (tid == 0) {
            double n = 8192.0;
            double sum_l2 = 2.0 * n * g_sqsum - 2.0 * sredc[0];
            double bw = sum_l2 / (n * n - n);
            bw /= 4.0;  // KERNEL_MUL ** (KERNEL_NUM // 2)
            const double LOG2E = 1.4426950408889634;
            g_cc = (float)(-LOG2E / (bw * 16.0));
            __threadfence();
            ((volatile int*)&g_ccflag)[0] = 1;
        }
        __syncthreads();   // before loads overwrite sm
    }

    // triangular block decode
    int idx = blockIdx.x;
    int bj = (int)((sqrtf(8.0f * (float)idx + 1.0f) - 1.0f) * 0.5f);
    while ((bj + 1) * (bj + 2) / 2 <= idx) bj++;
    while (bj * (bj + 1) / 2 > idx) bj--;
    int bi = idx - bj * (bj + 1) / 2;
    int rowA = bi * 128, rowB = bj * 128;

    // ---- stage loader --------------------------------------------------------
    int r0 = tid >> 3, c16 = tid & 7;
    uint32_t soff = (uint32_t)(r0 * 128 + ((c16 ^ (r0 & 7)) << 4));
    const __half* gA = g_data + (size_t)(rowA + r0) * 512 + c16 * 8;
    const __half* gB = g_data + (size_t)(rowB + r0) * 512 + c16 * 8;

    auto load_full = [&](int kt, uint32_t stg) {
        const __half* pa = gA + kt * 64;
        const __half* pb = gB + kt * 64;
#pragma unroll
        for (int i = 0; i < 8; i++)
            cp_async16(stg + soff + i * 2048, pa + i * 8192);
#pragma unroll
        for (int i = 0; i < 8; i++)
            cp_async16(stg + A_BYTES + soff + i * 2048, pb + i * 8192);
        CP_COMMIT();
    };
    auto load_quarter = [&](int kt, uint32_t stg, int s) {
        const __half* pa = gA + kt * 64;
        const __half* pb = gB + kt * 64;
#pragma unroll
        for (int i = 2 * s; i < 2 * s + 2; i++) {
            cp_async16(stg + soff + i * 2048, pa + i * 8192);
            cp_async16(stg + A_BYTES + soff + i * 2048, pb + i * 8192);
        }
    };

    load_full(0, sbase);
    load_full(1, sbase + STAGE_BYTES);

    int wm = (wid >> 1) * 64;
    int wn = (wid & 1) * 64;

    int mat = lane >> 3, r8 = lane & 7;
    int lrow = (mat & 1) * 8 + r8;
    int lhi  = mat >> 1;

    uint32_t aoff0[4], boff0[4];
#pragma unroll
    for (int mt = 0; mt < 4; mt++) {
        int m = wm + mt * 16 + lrow;
        aoff0[mt] = m * 128 + ((lhi ^ (m & 7)) << 4);
    }
#pragma unroll
    for (int g = 0; g < 4; g++) {
        int n = wn + g * 16 + lrow;
        boff0[g] = A_BYTES + n * 128 + ((lhi ^ (n & 7)) << 4);
    }

    float acc[4][8][4];
#pragma unroll
    for (int a = 0; a < 4; a++)
#pragma unroll
        for (int b = 0; b < 8; b++)
#pragma unroll
            for (int c = 0; c < 4; c++) acc[a][b][c] = 0.f;

    uint32_t af[2][4];       // A frags, per-mt pipeline
    uint32_t bf[2][4][4];    // B frags, per-phase double buffer

    auto ldA = [&](uint32_t* a, uint32_t stg, int s, int mt) {
        ldsm4(a[0], a[1], a[2], a[3], stg + (aoff0[mt] ^ (uint32_t)(s << 5)));
    };
    auto ldB = [&](int b, uint32_t stg, int s) {
        uint32_t kx = (uint32_t)(s << 5);
#pragma unroll
        for (int g = 0; g < 4; g++)
            ldsm4(bf[b][g][0], bf[b][g][1], bf[b][g][2], bf[b][g][3],
                  stg + (boff0[g] ^ kx));
    };
    auto hmma8 = [&](int mt, const uint32_t* a, int b) {
#pragma unroll
        for (int nt = 0; nt < 8; nt++)
            hmma(acc[mt][nt], a,
                 bf[b][nt >> 1][nt & 1], bf[b][nt >> 1][(nt & 1) + 2]);
    };

    uint32_t stg_c = sbase;
    uint32_t stg_n = sbase + STAGE_BYTES;
    uint32_t stg_l = sbase + 2 * STAGE_BYTES;

    // prologue: chunk 0 ready; preload phase-0 B frags + (0,0) A frag
    CP_WAIT1();
    __syncthreads();
    ldB(0, stg_c, 0);
    ldA(af[0], stg_c, 0, 0);

    for (int kt = 0; kt < KT; kt++) {
        bool pref = (kt + 2 < KT);
#pragma unroll
        for (int s = 0; s < 4; s++) {
            if (pref) load_quarter(kt + 2, stg_l, s);   // spread LDGSTS
            if (s == 3) CP_COMMIT();                    // one group per chunk
#pragma unroll
            for (int mt = 0; mt < 4; mt++) {
                int cur = mt & 1, nxt = cur ^ 1;
                if (mt < 3)      ldA(af[nxt], stg_c, s, mt + 1);
                else if (s < 3) { ldB((s + 1) & 1, stg_c, s + 1);
                                  ldA(af[nxt], stg_c, s + 1, 0); }
                hmma8(mt, af[cur], s & 1);
            }
        }

        // all stg_c reads issued; drain + barrier, then preload next chunk
        CP_WAIT1();
        __syncthreads();
        if (kt + 1 < KT) {
            ldB(0, stg_n, 0);
            ldA(af[0], stg_n, 0, 0);
        }

        uint32_t t = stg_c; stg_c = stg_n; stg_n = stg_l; stg_l = t;
    }

    // ---- epilogue ------------------------------------------------------------
    float* s_sq = (float*)sm;
    double* sred = (double*)(sm + 1024);
    s_sq[tid] = g_sq[rowA + tid];
    s_sq[tid + 128] = g_sq[rowB + tid];
    if (tid == 0) {
        while (((volatile int*)&g_ccflag)[0] == 0) __nanosleep(64);
    }
    __syncthreads();
    __threadfence();

    float cc = g_cc;
    int er = lane >> 2, ec = (lane & 3) * 2;
    float fsum = 0.f;
#pragma unroll
    for (int mt = 0; mt < 4; mt++) {
        float sqi0 = s_sq[wm + mt * 16 + er];
        float sqi1 = s_sq[wm + mt * 16 + er + 8];
#pragma unroll
        for (int nt = 0; nt < 8; nt++) {
            float sqj0 = s_sq[128 + wn + nt * 8 + ec];
            float sqj1 = s_sq[128 + wn + nt * 8 + ec + 1];
            float d0 = acc[mt][nt][0], d1 = acc[mt][nt][1];
            float d2 = acc[mt][nt][2], d3 = acc[mt][nt][3];
            float l0 = fmaxf(fmaf(-2.f, d0, sqi0 + sqj0), 0.f);
            float l1 = fmaxf(fmaf(-2.f, d1, sqi0 + sqj1), 0.f);
            float l2 = fmaxf(fmaf(-2.f, d2, sqi1 + sqj0), 0.f);
            float l3 = fmaxf(fmaf(-2.f, d3, sqi1 + sqj1), 0.f);
            float t0 = ex2f(l0 * cc), t1 = ex2f(l1 * cc);
            float t2 = ex2f(l2 * cc), t3 = ex2f(l3 * cc);
            {
                float a2 = t0 * t0, a4 = a2 * a2, a8 = a4 * a4;
                fsum += ((t0 + a2) + (a4 + a8)) + a8 * a8;
            }
            {
                float a2 = t1 * t1, a4 = a2 * a2, a8 = a4 * a4;
                fsum += ((t1 + a2) + (a4 + a8)) + a8 * a8;
            }
            {
                float a2 = t2 * t2, a4 = a2 * a2, a8 = a4 * a4;
                fsum += ((t2 + a2) + (a4 + a8)) + a8 * a8;
            }
            {
                float a2 = t3 * t3, a4 = a2 * a2, a8 = a4 * a4;
                fsum += ((t3 + a2) + (a4 + a8)) + a8 * a8;
            }
        }
    }

#pragma unroll
    for (int o = 16; o; o >>= 1) fsum += __shfl_xor_sync(0xffffffffu, fsum, o);
    if (lane == 0) sred[wid] = (double)fsum;
    __syncthreads();
    if (tid == 0) {
        double tot = (sred[0] + sred[1]) + (sred[2] + sred[3]);
        int hi = (bi >= 32), hj = (bj >= 32);
        atomicAdd(&g_acc[hi * 2 + hj], tot);
        if (bi != bj) atomicAdd(&g_acc[hj * 2 + hi], tot);
        __threadfence();
        if (atomicAdd(&g_done2, 1) == 2079) {
            __threadfence();
            double inv = 1.0 / (4096.0 * 4096.0);
            out[0] = (float)((g_acc[0] + g_acc[3] - g_acc[1] - g_acc[2]) * inv);
            // reset all replay state
            g_acc[0] = g_acc[1] = g_acc[2] = g_acc[3] = 0.0;
            g_sqsum = 0.0;
            for (int i = 0; i < 512; i++) g_colA[i] = 0.f;
            g_ccflag = 0;
            g_done2 = 0;
        }
    }
}

// ---------------- launcher ---------------------------------------------------
extern "C" void kernel_launch(void* const* d_in, const int* in_sizes, int n_in,
                              void* d_out, int out_size) {
    const float* src = (const float*)d_in[0];
    const float* tgt = (const float*)d_in[1];
    float* out = (float*)d_out;

    cudaFuncSetAttribute(k_mma, cudaFuncAttributeMaxDynamicSharedMemorySize, SMEM_TOTAL);

    k_prep<<<512, 256>>>(src, tgt);
    k_mma<<<2080, 128, SMEM_TOTAL>>>(out);
}

// round 15
// speedup vs baseline: 1.0870x; 1.0870x over previous
#include <cuda_runtime.h>
#include <cuda_fp16.h>
#include <math.h>
#include <stdint.h>

typedef unsigned long long ull;

// ---------------- device globals (scratch; no allocations allowed) ----------
__device__ __half  g_data[8192 * 512]; // fp16 concatenated [source; target]
__device__ float   g_sq[8192];         // per-row squared L2 norms (fp32)
__device__ float   g_colA[512];        // column sums (atomic accum)
__device__ double  g_sqsum;            // total sq-norm sum (atomic accum)
__device__ int     g_done2;            // gemm CTA completion counter
__device__ int     g_ccflag;           // bandwidth coefficient ready
__device__ double  g_acc[4];           // quadrant sums [XX, XY, YX, YY]
__device__ float   g_cc;               // -log2(e) / (bw * 16)

static constexpr int NTILES = 2080;
static constexpr int GRID   = 304;     // 2 per SM x 152 SMs

// ---------------- PTX helpers ----------------------------------------------
__device__ __forceinline__ float ex2f(float x) {
    float y; asm("ex2.approx.ftz.f32 %0, %1;" : "=f"(y) : "f"(x)); return y;
}
__device__ __forceinline__ uint32_t smem_u32(const void* p) {
    uint32_t a;
    asm("{ .reg .u64 t; cvta.to.shared.u64 t, %1; cvt.u32.u64 %0, t; }" : "=r"(a) : "l"(p));
    return a;
}
__device__ __forceinline__ void cp_async16(uint32_t saddr, const void* g) {
    asm volatile("cp.async.cg.shared.global [%0], [%1], 16;" :: "r"(saddr), "l"(g));
}
#define CP_COMMIT()  asm volatile("cp.async.commit_group;" ::: "memory")
#define CP_WAIT1()   asm volatile("cp.async.wait_group 1;" ::: "memory")
#define CP_WAIT0()   asm volatile("cp.async.wait_group 0;" ::: "memory")

__device__ __forceinline__ void ldsm4(uint32_t& r0, uint32_t& r1, uint32_t& r2,
                                      uint32_t& r3, uint32_t addr) {
    asm volatile("ldmatrix.sync.aligned.m8n8.x4.shared.b16 {%0,%1,%2,%3}, [%4];"
                 : "=r"(r0), "=r"(r1), "=r"(r2), "=r"(r3) : "r"(addr));
}
__device__ __forceinline__ void hmma(float* d, const uint32_t* a, uint32_t b0, uint32_t b1) {
    asm volatile(
        "mma.sync.aligned.m16n8k16.row.col.f32.f16.f16.f32 "
        "{%0,%1,%2,%3}, {%4,%5,%6,%7}, {%8,%9}, {%0,%1,%2,%3};"
        : "+f"(d[0]), "+f"(d[1]), "+f"(d[2]), "+f"(d[3])
        : "r"(a[0]), "r"(a[1]), "r"(a[2]), "r"(a[3]), "r"(b0), "r"(b1));
}
// packed f32x2 helpers
__device__ __forceinline__ ull pk2(float a, float b) {
    ull r; asm("mov.b64 %0, {%1, %2};" : "=l"(r) : "f"(a), "f"(b)); return r;
}
__device__ __forceinline__ void upk2(ull v, float& a, float& b) {
    asm("mov.b64 {%0, %1}, %2;" : "=f"(a), "=f"(b) : "l"(v));
}
__device__ __forceinline__ ull mul2(ull a, ull b) {
    ull r; asm("mul.rn.f32x2 %0, %1, %2;" : "=l"(r) : "l"(a), "l"(b)); return r;
}
__device__ __forceinline__ ull add2(ull a, ull b) {
    ull r; asm("add.rn.f32x2 %0, %1, %2;" : "=l"(r) : "l"(a), "l"(b)); return r;
}
__device__ __forceinline__ ull fma2(ull a, ull b, ull c) {
    ull r; asm("fma.rn.f32x2 %0, %1, %2, %3;" : "=l"(r) : "l"(a), "l"(b), "l"(c)); return r;
}

// ---------------- kernel 1: prep (pure producer) ----------------------------
__global__ __launch_bounds__(256)
void k_prep(const float* __restrict__ src, const float* __restrict__ tgt) {
    __shared__ float scol[512];
    int tid = threadIdx.x, w = tid >> 5, lane = tid & 31;

    for (int i = tid; i < 512; i += 256) scol[i] = 0.f;

    int row0 = blockIdx.x * 16 + w * 2;
    const float* p0 = (row0 < 4096) ? src + (size_t)row0 * 512
                                    : tgt + (size_t)(row0 - 4096) * 512;
    const float* p1 = p0 + 512;

    float4 v[2][4];
#pragma unroll
    for (int c = 0; c < 4; c++) v[0][c] = *(const float4*)(p0 + lane * 4 + c * 128);
#pragma unroll
    for (int c = 0; c < 4; c++) v[1][c] = *(const float4*)(p1 + lane * 4 + c * 128);

    float colacc[16];
#pragma unroll
    for (int i = 0; i < 16; i++) colacc[i] = 0.f;
    double warp_sq = 0.0;
    __syncthreads();

#pragma unroll
    for (int rr = 0; rr < 2; rr++) {
        int row = row0 + rr;
        float s = 0.f;
#pragma unroll
        for (int c = 0; c < 4; c++) {
            float4 q = v[rr][c];
            uint2 o;
            asm("cvt.rn.f16x2.f32 %0, %1, %2;" : "=r"(o.x) : "f"(q.y), "f"(q.x));
            asm("cvt.rn.f16x2.f32 %0, %1, %2;" : "=r"(o.y) : "f"(q.w), "f"(q.z));
            *(uint2*)(g_data + (size_t)row * 512 + lane * 4 + c * 128) = o;
            s = fmaf(q.x, q.x, s); s = fmaf(q.y, q.y, s);
            s = fmaf(q.z, q.z, s); s = fmaf(q.w, q.w, s);
            colacc[c * 4 + 0] += q.x; colacc[c * 4 + 1] += q.y;
            colacc[c * 4 + 2] += q.z; colacc[c * 4 + 3] += q.w;
        }
#pragma unroll
        for (int o = 16; o; o >>= 1) s += __shfl_xor_sync(0xffffffffu, s, o);
        if (lane == 0) { g_sq[row] = s; warp_sq += (double)s; }
    }

#pragma unroll
    for (int c = 0; c < 4; c++)
#pragma unroll
        for (int j = 0; j < 4; j++)
            atomicAdd(&scol[lane * 4 + c * 128 + j], colacc[c * 4 + j]);
    __syncthreads();

    for (int i = tid; i < 512; i += 256) atomicAdd(&g_colA[i], scol[i]);
    if (lane == 0) atomicAdd(&g_sqsum, warp_sq);
}

// ---------------- kernel 2: persistent fp16 GEMM + epilogue + final ---------
// 304 persistent CTAs; tiles = triangular 64x64 blocks of 128x128 (2080).
// 4 warps (2m x 2n), warp tile 64x64, 2 CTAs/SM, K=512 in 8 chunks of 64,
// 3-stage cp.async pipeline continuing seamlessly ACROSS tiles.
static constexpr int KT = 8;
static constexpr int A_BYTES = 16384;       // 128 rows x 128B
static constexpr int STAGE_BYTES = 32768;   // A 16KB + B 16KB
static constexpr int EPI_OFF = 3 * STAGE_BYTES;      // dedicated epilogue smem
static constexpr int SMEM_TOTAL = EPI_OFF + 1024 + 64;

__global__ __launch_bounds__(128, 2)
void k_mma(float* __restrict__ out) {
    extern __shared__ char sm[];
    uint32_t sbase = smem_u32(sm);
    float*  s_sq = (float*)(sm + EPI_OFF);
    double* sred = (double*)(sm + EPI_OFF + 1024);

    int tid = threadIdx.x;
    int wid = tid >> 5, lane = tid & 31;

    // CTA 0: compute g_cc (inputs complete at kernel boundary), publish flag.
    if (blockIdx.x == 0) {
        double* sredc = (double*)(sm + EPI_OFF);
        double csq = 0.0;
#pragma unroll
        for (int j = 0; j < 4; j++) {
            double c = (double)g_colA[tid + j * 128];
            csq += c * c;
        }
        sredc[tid] = csq;
        __syncthreads();
        for (int o = 64; o; o >>= 1) { if (tid < o) sredc[tid] += sredc[tid + o]; __syncthreads(); }
        if (tid == 0) {
            double n = 8192.0;
            double sum_l2 = 2.0 * n * g_sqsum - 2.0 * sredc[0];
            double bw = sum_l2 / (n * n - n);
            bw /= 4.0;  // KERNEL_MUL ** (KERNEL_NUM // 2)
            const double LOG2E = 1.4426950408889634;
            g_cc = (float)(-LOG2E / (bw * 16.0));
            __threadfence();
            ((volatile int*)&g_ccflag)[0] = 1;
        }
        __syncthreads();
    }

    auto decode = [](int t, int& Bi, int& Bj) {
        int J = (int)((sqrtf(8.0f * (float)t + 1.0f) - 1.0f) * 0.5f);
        while ((J + 1) * (J + 2) / 2 <= t) J++;
        while (J * (J + 1) / 2 > t) J--;
        Bi = t - J * (J + 1) / 2; Bj = J;
    };

    // loader thread mapping (tile-independent)
    int r0 = tid >> 3, c16 = tid & 7;
    uint32_t soff = (uint32_t)(r0 * 128 + ((c16 ^ (r0 & 7)) << 4));
    size_t goff = (size_t)r0 * 512 + c16 * 8;

    auto load_stage = [&](const __half* gA, const __half* gB, int kt, uint32_t stg) {
        const __half* pa = gA + kt * 64;
        const __half* pb = gB + kt * 64;
#pragma unroll
        for (int i = 0; i < 8; i++)
            cp_async16(stg + soff + i * 2048, pa + i * 8192);
#pragma unroll
        for (int i = 0; i < 8; i++)
            cp_async16(stg + A_BYTES + soff + i * 2048, pb + i * 8192);
        CP_COMMIT();
    };

    int wm = (wid >> 1) * 64;
    int wn = (wid & 1) * 64;

    int mat = lane >> 3, r8 = lane & 7;
    int lrow = (mat & 1) * 8 + r8;
    int lhi  = mat >> 1;

    uint32_t aoff0[4], boff0[4];
#pragma unroll
    for (int mt = 0; mt < 4; mt++) {
        int m = wm + mt * 16 + lrow;
        aoff0[mt] = m * 128 + ((lhi ^ (m & 7)) << 4);
    }
#pragma unroll
    for (int g = 0; g < 4; g++) {
        int n = wn + g * 16 + lrow;
        boff0[g] = A_BYTES + n * 128 + ((lhi ^ (n & 7)) << 4);
    }

    float acc[4][8][4];
#pragma unroll
    for (int a = 0; a < 4; a++)
#pragma unroll
        for (int b = 0; b < 8; b++)
#pragma unroll
            for (int c = 0; c < 4; c++) acc[a][b][c] = 0.f;

    uint32_t af[2][4][4], bf[2][4][4];
    auto frag_load = [&](int b, uint32_t stg, int ksx) {
        uint32_t kx = (uint32_t)(ksx << 5);
#pragma unroll
        for (int mt = 0; mt < 4; mt++)
            ldsm4(af[b][mt][0], af[b][mt][1], af[b][mt][2], af[b][mt][3],
                  stg + (aoff0[mt] ^ kx));
#pragma unroll
        for (int g = 0; g < 4; g++)
            ldsm4(bf[b][g][0], bf[b][g][1], bf[b][g][2], bf[b][g][3],
                  stg + (boff0[g] ^ kx));
    };
    auto frag_mma = [&](int b) {
#pragma unroll
        for (int mt = 0; mt < 4; mt++)
#pragma unroll
            for (int nt = 0; nt < 8; nt++)
                hmma(acc[mt][nt], af[b][mt],
                     bf[b][nt >> 1][nt & 1], bf[b][nt >> 1][(nt & 1) + 2]);
    };

    uint32_t stg_c = sbase;
    uint32_t stg_n = sbase + STAGE_BYTES;
    uint32_t stg_l = sbase + 2 * STAGE_BYTES;

    // first tile
    int tile = blockIdx.x;
    int bi, bj; decode(tile, bi, bj);
    int rowA = bi * 128, rowB = bj * 128;
    const __half* gA = g_data + (size_t)rowA * 512 + goff;
    const __half* gB = g_data + (size_t)rowB * 512 + goff;

    load_stage(gA, gB, 0, stg_c);
    load_stage(gA, gB, 1, stg_n);
    CP_WAIT1();
    __syncthreads();
    frag_load(0, stg_c, 0);

    int er = lane >> 2, ec = (lane & 3) * 2;
    const ull neg2 = pk2(-2.f, -2.f);

    while (true) {
        int ntile = tile + GRID;
        bool have_next = (ntile < NTILES);
        int nbi, nbj; decode(have_next ? ntile : tile, nbi, nbj);
        const __half* ngA = g_data + (size_t)(nbi * 128) * 512 + goff;
        const __half* ngB = g_data + (size_t)(nbj * 128) * 512 + goff;

        for (int kt = 0; kt < KT; kt++) {
            frag_load(1, stg_c, 1);
            if (kt < KT - 2) load_stage(gA, gB, kt + 2, stg_l);
            else             load_stage(ngA, ngB, kt - (KT - 2), stg_l);
            frag_mma(0);

            frag_load(0, stg_c, 2);
            frag_mma(1);
            frag_load(1, stg_c, 3);
            frag_mma(0);

            CP_WAIT1();
            __syncthreads();
            frag_load(0, stg_n, 0);   // chunk kt+1 phase0 (or next tile c0 at kt=7)
            frag_mma(1);

            uint32_t t = stg_c; stg_c = stg_n; stg_n = stg_l; stg_l = t;
        }

        // ---- epilogue (overlaps next tile's c1 load in flight) --------------
        s_sq[tid] = g_sq[rowA + tid];
        s_sq[tid + 128] = g_sq[rowB + tid];
        if (tid == 0) {
            while (((volatile int*)&g_ccflag)[0] == 0) __nanosleep(64);
        }
        __syncthreads();
        __threadfence();

        float cc = g_cc;
        ull cc2 = pk2(cc, cc);
        ull fsum2 = 0ull;
#pragma unroll
        for (int mt = 0; mt < 4; mt++) {
            float sqi0 = s_sq[wm + mt * 16 + er];
            float sqi1 = s_sq[wm + mt * 16 + er + 8];
            ull si0 = pk2(sqi0, sqi0), si1 = pk2(sqi1, sqi1);
#pragma unroll
            for (int nt = 0; nt < 8; nt++) {
                float2 sj = *(float2*)&s_sq[128 + wn + nt * 8 + ec];
                ull sj2 = pk2(sj.x, sj.y);
                ull dA = pk2(acc[mt][nt][0], acc[mt][nt][1]);
                ull dB = pk2(acc[mt][nt][2], acc[mt][nt][3]);
                ull uA = mul2(fma2(neg2, dA, add2(si0, sj2)), cc2);
                ull uB = mul2(fma2(neg2, dB, add2(si1, sj2)), cc2);
                float u0, u1, u2, u3;
                upk2(uA, u0, u1); upk2(uB, u2, u3);
                // l2 clamp: cc<0 so clamp u to <= 0
                float t0 = ex2f(fminf(u0, 0.f)), t1 = ex2f(fminf(u1, 0.f));
                float t2 = ex2f(fminf(u2, 0.f)), t3 = ex2f(fminf(u3, 0.f));
                ull TA = pk2(t0, t1), TB = pk2(t2, t3);
                ull A2 = mul2(TA, TA), A4 = mul2(A2, A2), A8 = mul2(A4, A4);
                ull SA = add2(add2(TA, A2), add2(A4, A8));
                SA = add2(SA, mul2(A8, A8));
                ull B2 = mul2(TB, TB), B4 = mul2(B2, B2), B8 = mul2(B4, B4);
                ull SB = add2(add2(TB, B2), add2(B4, B8));
                SB = add2(SB, mul2(B8, B8));
                fsum2 = add2(fsum2, add2(SA, SB));
            }
        }
        float fa, fb;
        upk2(fsum2, fa, fb);
        float fsum = fa + fb;
#pragma unroll
        for (int o = 16; o; o >>= 1) fsum += __shfl_xor_sync(0xffffffffu, fsum, o);
        if (lane == 0) sred[wid] = (double)fsum;
        __syncthreads();
        if (tid == 0) {
            double tot = (sred[0] + sred[1]) + (sred[2] + sred[3]);
            int hi = (bi >= 32), hj = (bj >= 32);
            atomicAdd(&g_acc[hi * 2 + hj], tot);
            if (bi != bj) atomicAdd(&g_acc[hj * 2 + hi], tot);
        }

        // zero accumulators for next tile
#pragma unroll
        for (int a = 0; a < 4; a++)
#pragma unroll
            for (int b = 0; b < 8; b++)
#pragma unroll
                for (int c = 0; c < 4; c++) acc[a][b][c] = 0.f;

        if (!have_next) break;
        tile = ntile; bi = nbi; bj = nbj;
        rowA = bi * 128; rowB = bj * 128;
        gA = ngA; gB = ngB;
        __syncthreads();   // epilogue smem writes done before reuse
    }

    CP_WAIT0();   // drain abandoned prefetches before exit
    __syncthreads();
    if (tid == 0) {
        __threadfence();
        if (atomicAdd(&g_done2, 1) == GRID - 1) {
            __threadfence();
            double inv = 1.0 / (4096.0 * 4096.0);
            out[0] = (float)((g_acc[0] + g_acc[3] - g_acc[1] - g_acc[2]) * inv);
            // reset all replay state
            g_acc[0] = g_acc[1] = g_acc[2] = g_acc[3] = 0.0;
            g_sqsum = 0.0;
            for (int i = 0; i < 512; i++) g_colA[i] = 0.f;
            g_ccflag = 0;
            g_done2 = 0;
        }
    }
}

// ---------------- launcher ---------------------------------------------------
extern "C" void kernel_launch(void* const* d_in, const int* in_sizes, int n_in,
                              void* d_out, int out_size) {
    const float* src = (const float*)d_in[0];
    const float* tgt = (const float*)d_in[1];
    float* out = (float*)d_out;

    cudaFuncSetAttribute(k_mma, cudaFuncAttributeMaxDynamicSharedMemorySize, SMEM_TOTAL);

    k_prep<<<512, 256>>>(src, tgt);
    k_mma<<<GRID, 128, SMEM_TOTAL>>>(out);
}